// round 15
// baseline (speedup 1.0000x reference)
#include <cuda_runtime.h>
#include <cuda_bf16.h>
#include <cuda_fp16.h>
#include <stdint.h>

// ---------------------------------------------------------------------------
// Problem constants
// ---------------------------------------------------------------------------
#define NMAX 100000
#define EMAX 3200000
#define F0 512
#define F1 256
#define F2 64

// ---------------------------------------------------------------------------
// Static device scratch
// ---------------------------------------------------------------------------
__device__ float d_xw1[NMAX * F1];
__device__ float d_h[NMAX * F1];
__device__ float d_hw2[NMAX * F2];
__device__ int   d_cnt[NMAX];
__device__ int   d_fill[NMAX];
__device__ int   d_rowptr[NMAX + 1];
__device__ int   d_cols[EMAX];
__device__ float d_vals[EMAX];
__device__ int   d_chunksums[128];
__device__ float d_sum1[F1], d_sumsq1[F1];
__device__ float d_sum2[F2], d_sumsq2[F2];
// W1 split: hi/lo fp16, layout [N=256][K=512] K-major
__device__ __align__(128) __half d_Bh[F1 * F0];
__device__ __align__(128) __half d_Bl[F1 * F0];
// W2 split: hi/lo fp16, layout [N=64][K=256] K-major
__device__ __align__(128) __half d_B2h[F2 * F1];
__device__ __align__(128) __half d_B2l[F2 * F1];

// ---------------------------------------------------------------------------
// Helpers
// ---------------------------------------------------------------------------
__device__ __forceinline__ uint32_t smem_u32(const void* p) {
    uint32_t a;
    asm("{ .reg .u64 t; cvta.to.shared.u64 t, %1; cvt.u32.u64 %0, t; }" : "=r"(a) : "l"(p));
    return a;
}
__device__ __forceinline__ uint32_t pack2hi_h(float a, float b) {
    __half2 t = __floats2half2_rn(a, b);
    return *(uint32_t*)&t;
}
__device__ __forceinline__ uint32_t pack2lo_h(float a, float b) {
    float ah = __half2float(__float2half_rn(a));
    float bh = __half2float(__float2half_rn(b));
    __half2 t = __floats2half2_rn(a - ah, b - bh);
    return *(uint32_t*)&t;
}
__device__ __forceinline__ void mma_f16(float* d, const uint32_t* a, uint32_t b0, uint32_t b1) {
    asm volatile(
        "mma.sync.aligned.m16n8k16.row.col.f32.f16.f16.f32 "
        "{%0,%1,%2,%3}, {%4,%5,%6,%7}, {%8,%9}, {%0,%1,%2,%3};"
        : "+f"(d[0]), "+f"(d[1]), "+f"(d[2]), "+f"(d[3])
        : "r"(a[0]), "r"(a[1]), "r"(a[2]), "r"(a[3]), "r"(b0), "r"(b1));
}
__device__ __forceinline__ void ldmatrix_x4(uint32_t* r, uint32_t addr) {
    asm volatile("ldmatrix.sync.aligned.m8n8.x4.shared.b16 {%0,%1,%2,%3}, [%4];"
                 : "=r"(r[0]), "=r"(r[1]), "=r"(r[2]), "=r"(r[3]) : "r"(addr));
}
__device__ __forceinline__ void cp_async16(uint32_t saddr, const void* gptr) {
    asm volatile("cp.async.ca.shared.global [%0], [%1], 16;" :: "r"(saddr), "l"(gptr));
}
__device__ __forceinline__ void cp_commit() {
    asm volatile("cp.async.commit_group;" ::: "memory");
}
__device__ __forceinline__ void cp_wait0() {
    asm volatile("cp.async.wait_group 0;" ::: "memory");
}

// ---------------------------------------------------------------------------
// Zero transient accumulators
// ---------------------------------------------------------------------------
__global__ void zero_kernel(int Nn) {
    int i = blockIdx.x * blockDim.x + threadIdx.x;
    if (i < Nn) { d_cnt[i] = 0; d_fill[i] = 0; }
    if (i < F1) { d_sum1[i] = 0.f; d_sumsq1[i] = 0.f; }
    if (i < F2) { d_sum2[i] = 0.f; d_sumsq2[i] = 0.f; }
}

// ---------------------------------------------------------------------------
// CSR build
// ---------------------------------------------------------------------------
__global__ void hist_kernel(const int* __restrict__ erow, int E) {
    int i = blockIdx.x * blockDim.x + threadIdx.x;
    if (i < E) atomicAdd(&d_cnt[erow[i]], 1);
}

__global__ void scanA_kernel(int Nn) {
    __shared__ int sh[1024];
    int gid = blockIdx.x * 1024 + threadIdx.x;
    int v = (gid < Nn) ? d_cnt[gid] : 0;
    sh[threadIdx.x] = v;
    __syncthreads();
#pragma unroll
    for (int off = 1; off < 1024; off <<= 1) {
        int t = (threadIdx.x >= off) ? sh[threadIdx.x - off] : 0;
        __syncthreads();
        sh[threadIdx.x] += t;
        __syncthreads();
    }
    if (gid < Nn) d_rowptr[gid] = sh[threadIdx.x] - v;
    if (threadIdx.x == 1023) d_chunksums[blockIdx.x] = sh[1023];
}

__global__ void scanB_kernel(int nch) {
    __shared__ int sh[128];
    int v = (threadIdx.x < nch) ? d_chunksums[threadIdx.x] : 0;
    sh[threadIdx.x] = v;
    __syncthreads();
#pragma unroll
    for (int off = 1; off < 128; off <<= 1) {
        int t = (threadIdx.x >= off) ? sh[threadIdx.x - off] : 0;
        __syncthreads();
        sh[threadIdx.x] += t;
        __syncthreads();
    }
    if (threadIdx.x < nch) d_chunksums[threadIdx.x] = sh[threadIdx.x] - v;
}

__global__ void scanC_kernel(int Nn, int E) {
    int gid = blockIdx.x * blockDim.x + threadIdx.x;
    if (gid < Nn) d_rowptr[gid] += d_chunksums[gid >> 10];
    if (gid == 0) d_rowptr[Nn] = E;
}

__global__ void scatter_kernel(const int* __restrict__ erow,
                               const int* __restrict__ ecol,
                               const float* __restrict__ eval, int E) {
    int i = blockIdx.x * blockDim.x + threadIdx.x;
    if (i < E) {
        int r = erow[i];
        int p = d_rowptr[r] + atomicAdd(&d_fill[r], 1);
        d_cols[p] = ecol[i];
        d_vals[p] = eval[i];
    }
}

// ---------------------------------------------------------------------------
// Weight prep: split W into fp16 hi + lo, transposed to K-major
// ---------------------------------------------------------------------------
__global__ void prepW1_kernel(const float* __restrict__ W1) {
    int i = blockIdx.x * blockDim.x + threadIdx.x;
    if (i >= F0 * F1) return;
    int k = i >> 8;
    int n = i & 255;
    float w = W1[i];
    __half h = __float2half_rn(w);
    __half l = __float2half_rn(w - __half2float(h));
    d_Bh[(size_t)n * F0 + k] = h;
    d_Bl[(size_t)n * F0 + k] = l;
}
__global__ void prepW2_kernel(const float* __restrict__ W2) {
    int i = blockIdx.x * blockDim.x + threadIdx.x;
    if (i >= F1 * F2) return;
    int k = i >> 6;
    int n = i & 63;
    float w = W2[i];
    __half h = __float2half_rn(w);
    __half l = __float2half_rn(w - __half2float(h));
    d_B2h[(size_t)n * F1 + k] = h;
    d_B2l[(size_t)n * F1 + k] = l;
}

// ---------------------------------------------------------------------------
// GEMM1 via mma.sync fp16 3-term: Ahi*Bhi + Alo*Bhi + Ahi*Blo
// Block tile 128x128; warp tile 32x64 (4x2 warps); 16 k-blocks of 32 fp32 cols.
// Buffer: A_hi 0 | A_lo 10240 | B_hi 20480 | B_lo 30720. Double-buffered.
// ---------------------------------------------------------------------------
#define PITCHB 80
#define BUFS1 40960
#define SMEM1 (2 * BUFS1)
#define KBLK1 16

__global__ void __launch_bounds__(256, 2)
gemm1_mma_kernel(const float* __restrict__ x, int M) {
    extern __shared__ __align__(16) char sm[];
    const int tid = threadIdx.x;
    const int wid = tid >> 5;
    const int lane = tid & 31;
    const int warp_m = wid & 3;
    const int warp_n = wid >> 2;
    const int gid = lane >> 2;
    const int tg = lane & 3;
    const int bm0 = blockIdx.x * 128;
    const int bn0 = blockIdx.y * 128;
    const uint32_t sb = smem_u32(sm);

    float acc[2][8][4];
#pragma unroll
    for (int mt = 0; mt < 2; mt++)
#pragma unroll
        for (int nt = 0; nt < 8; nt++)
#pragma unroll
            for (int q = 0; q < 4; q++) acc[mt][nt][q] = 0.f;

    const int arow = tid >> 3;
    const int af4 = tid & 7;
    const int brow = tid >> 2;
    const int bq = tid & 3;

    // ---- prologue: k-block 0
    {
#pragma unroll
        for (int i = 0; i < 4; i++) {
            int row = arow + i * 32;
            int rg = bm0 + row;
            float4 f = make_float4(0.f, 0.f, 0.f, 0.f);
            if (rg < M) f = *(const float4*)(x + (size_t)rg * F0 + af4 * 4);
            *(uint2*)(sm + row * PITCHB + af4 * 8) =
                make_uint2(pack2hi_h(f.x, f.y), pack2hi_h(f.z, f.w));
            *(uint2*)(sm + 10240 + row * PITCHB + af4 * 8) =
                make_uint2(pack2lo_h(f.x, f.y), pack2lo_h(f.z, f.w));
        }
#pragma unroll
        for (int i = 0; i < 2; i++) {
            int row = brow + i * 64;
            cp_async16(sb + 20480 + row * PITCHB + bq * 16,
                       d_Bh + (size_t)(bn0 + row) * F0 + bq * 8);
            cp_async16(sb + 30720 + row * PITCHB + bq * 16,
                       d_Bl + (size_t)(bn0 + row) * F0 + bq * 8);
        }
        cp_commit();
        cp_wait0();
        __syncthreads();
    }

    for (int c = 0; c < KBLK1; c++) {
        const int buf = c & 1;
        float4 fa[4];
        const bool have = (c + 1 < KBLK1);
        if (have) {
            const int sk0 = (c + 1) * 32;
#pragma unroll
            for (int i = 0; i < 4; i++) {
                int row = arow + i * 32;
                int rg = bm0 + row;
                fa[i] = make_float4(0.f, 0.f, 0.f, 0.f);
                if (rg < M) fa[i] = *(const float4*)(x + (size_t)rg * F0 + sk0 + af4 * 4);
            }
            const uint32_t bb = sb + (buf ^ 1) * BUFS1;
#pragma unroll
            for (int i = 0; i < 2; i++) {
                int row = brow + i * 64;
                cp_async16(bb + 20480 + row * PITCHB + bq * 16,
                           d_Bh + (size_t)(bn0 + row) * F0 + sk0 + bq * 8);
                cp_async16(bb + 30720 + row * PITCHB + bq * 16,
                           d_Bl + (size_t)(bn0 + row) * F0 + sk0 + bq * 8);
            }
            cp_commit();
        }
        // ---- compute on buf
        const uint32_t sA = sb + buf * BUFS1;
        const char* Bh = sm + buf * BUFS1 + 20480;
        const char* Bl = sm + buf * BUFS1 + 30720;
#pragma unroll
        for (int ks = 0; ks < 2; ks++) {
            uint32_t ahi[2][4], alo[2][4];
#pragma unroll
            for (int mt = 0; mt < 2; mt++) {
                uint32_t rowoff = (warp_m * 32 + mt * 16 + (lane & 15)) * PITCHB
                                  + ks * 32 + (lane >> 4) * 16;
                ldmatrix_x4(ahi[mt], sA + rowoff);
                ldmatrix_x4(alo[mt], sA + 10240 + rowoff);
            }
#pragma unroll
            for (int nt = 0; nt < 8; nt++) {
                uint32_t roff = (warp_n * 64 + nt * 8 + gid) * PITCHB + ks * 32 + tg * 4;
                uint32_t bh0 = *(const uint32_t*)(Bh + roff);
                uint32_t bh1 = *(const uint32_t*)(Bh + roff + 16);
                uint32_t bl0 = *(const uint32_t*)(Bl + roff);
                uint32_t bl1 = *(const uint32_t*)(Bl + roff + 16);
                mma_f16(acc[0][nt], ahi[0], bh0, bh1);
                mma_f16(acc[1][nt], ahi[1], bh0, bh1);
                mma_f16(acc[0][nt], alo[0], bh0, bh1);
                mma_f16(acc[1][nt], alo[1], bh0, bh1);
                mma_f16(acc[0][nt], ahi[0], bl0, bl1);
                mma_f16(acc[1][nt], ahi[1], bl0, bl1);
            }
        }
        if (have) {
            char* dA = sm + (buf ^ 1) * BUFS1;
#pragma unroll
            for (int i = 0; i < 4; i++) {
                int row = arow + i * 32;
                *(uint2*)(dA + row * PITCHB + af4 * 8) =
                    make_uint2(pack2hi_h(fa[i].x, fa[i].y), pack2hi_h(fa[i].z, fa[i].w));
                *(uint2*)(dA + 10240 + row * PITCHB + af4 * 8) =
                    make_uint2(pack2lo_h(fa[i].x, fa[i].y), pack2lo_h(fa[i].z, fa[i].w));
            }
        }
        cp_wait0();
        __syncthreads();
    }

    // ---- epilogue: write fp32 result
#pragma unroll
    for (int mt = 0; mt < 2; mt++) {
        int r0 = bm0 + warp_m * 32 + mt * 16 + gid;
        int r1 = r0 + 8;
#pragma unroll
        for (int nt = 0; nt < 8; nt++) {
            int col = bn0 + warp_n * 64 + nt * 8 + tg * 2;
            if (r0 < M)
                *(float2*)(d_xw1 + (size_t)r0 * F1 + col) =
                    make_float2(acc[mt][nt][0], acc[mt][nt][1]);
            if (r1 < M)
                *(float2*)(d_xw1 + (size_t)r1 * F1 + col) =
                    make_float2(acc[mt][nt][2], acc[mt][nt][3]);
        }
    }
}

// ---------------------------------------------------------------------------
// GEMM2 via mma.sync fp16 3-term: hw2 = relu(bn1(h)) @ W2
// BN1 finalize fused at kernel start.
// ---------------------------------------------------------------------------
#define BUFS2 30720
#define SMEM2 (2 * BUFS2)
#define KBLK2 8

__global__ void __launch_bounds__(256, 2)
gemm2_mma_kernel(const float* __restrict__ g1, const float* __restrict__ b1, int M) {
    extern __shared__ __align__(16) char sm[];
    __shared__ float s_sc[F1], s_bi[F1];
    const int tid = threadIdx.x;
    const int wid = tid >> 5;
    const int lane = tid & 31;
    const int gid = lane >> 2;
    const int tg = lane & 3;
    const int bm0 = blockIdx.x * 128;
    const uint32_t sb = smem_u32(sm);

    // fused BN1 finalize
    {
        float inv = 1.f / (float)M;
        float mean = d_sum1[tid] * inv;
        float var = d_sumsq1[tid] * inv - mean * mean;
        float rs = rsqrtf(var + 1e-5f);
        float sc = g1[tid] * rs;
        s_sc[tid] = sc;
        s_bi[tid] = b1[tid] - mean * sc;
    }
    __syncthreads();

    float acc[8][4];
#pragma unroll
    for (int nt = 0; nt < 8; nt++)
#pragma unroll
        for (int q = 0; q < 4; q++) acc[nt][q] = 0.f;

    const int arow = tid >> 3;
    const int af4 = tid & 7;
    const int brow = tid >> 2;
    const int bq = tid & 3;

    auto packA = [&](char* dst, int sk0) {
#pragma unroll
        for (int i = 0; i < 4; i++) {
            int row = arow + i * 32;
            int rg = bm0 + row;
            float4 f = make_float4(0.f, 0.f, 0.f, 0.f);
            if (rg < M) {
                f = __ldcs((const float4*)(d_h + (size_t)rg * F1 + sk0 + af4 * 4));
                int cb = sk0 + af4 * 4;
                f.x = fmaxf(fmaf(f.x, s_sc[cb + 0], s_bi[cb + 0]), 0.f);
                f.y = fmaxf(fmaf(f.y, s_sc[cb + 1], s_bi[cb + 1]), 0.f);
                f.z = fmaxf(fmaf(f.z, s_sc[cb + 2], s_bi[cb + 2]), 0.f);
                f.w = fmaxf(fmaf(f.w, s_sc[cb + 3], s_bi[cb + 3]), 0.f);
            }
            *(uint2*)(dst + row * PITCHB + af4 * 8) =
                make_uint2(pack2hi_h(f.x, f.y), pack2hi_h(f.z, f.w));
            *(uint2*)(dst + 10240 + row * PITCHB + af4 * 8) =
                make_uint2(pack2lo_h(f.x, f.y), pack2lo_h(f.z, f.w));
        }
    };

    packA(sm, 0);
    cp_async16(sb + 20480 + brow * PITCHB + bq * 16, d_B2h + (size_t)brow * F1 + bq * 8);
    cp_async16(sb + 25600 + brow * PITCHB + bq * 16, d_B2l + (size_t)brow * F1 + bq * 8);
    cp_commit();
    cp_wait0();
    __syncthreads();

    for (int c = 0; c < KBLK2; c++) {
        const int buf = c & 1;
        const bool have = (c + 1 < KBLK2);
        if (have) {
            const int sk0 = (c + 1) * 32;
            const uint32_t bb = sb + (buf ^ 1) * BUFS2;
            cp_async16(bb + 20480 + brow * PITCHB + bq * 16,
                       d_B2h + (size_t)brow * F1 + sk0 + bq * 8);
            cp_async16(bb + 25600 + brow * PITCHB + bq * 16,
                       d_B2l + (size_t)brow * F1 + sk0 + bq * 8);
            cp_commit();
        }
        const uint32_t sA = sb + buf * BUFS2;
        const char* Bh = sm + buf * BUFS2 + 20480;
        const char* Bl = sm + buf * BUFS2 + 25600;
#pragma unroll
        for (int ks = 0; ks < 2; ks++) {
            uint32_t ahi[4], alo[4];
            uint32_t rowoff = (wid * 16 + (lane & 15)) * PITCHB + ks * 32 + (lane >> 4) * 16;
            ldmatrix_x4(ahi, sA + rowoff);
            ldmatrix_x4(alo, sA + 10240 + rowoff);
#pragma unroll
            for (int nt = 0; nt < 8; nt++) {
                uint32_t roff = (nt * 8 + gid) * PITCHB + ks * 32 + tg * 4;
                uint32_t bh0 = *(const uint32_t*)(Bh + roff);
                uint32_t bh1 = *(const uint32_t*)(Bh + roff + 16);
                uint32_t bl0 = *(const uint32_t*)(Bl + roff);
                uint32_t bl1 = *(const uint32_t*)(Bl + roff + 16);
                mma_f16(acc[nt], ahi, bh0, bh1);
                mma_f16(acc[nt], alo, bh0, bh1);
                mma_f16(acc[nt], ahi, bl0, bl1);
            }
        }
        if (have) packA(sm + (buf ^ 1) * BUFS2, (c + 1) * 32);
        cp_wait0();
        __syncthreads();
    }

    // ---- epilogue
    int r0 = bm0 + wid * 16 + gid;
    int r1 = r0 + 8;
#pragma unroll
    for (int nt = 0; nt < 8; nt++) {
        int col = nt * 8 + tg * 2;
        if (r0 < M)
            *(float2*)(d_hw2 + (size_t)r0 * F2 + col) = make_float2(acc[nt][0], acc[nt][1]);
        if (r1 < M)
            *(float2*)(d_hw2 + (size_t)r1 * F2 + col) = make_float2(acc[nt][2], acc[nt][3]);
    }
}

// ---------------------------------------------------------------------------
// SpMM1 (persistent): h = relu(A_sparse @ xw1), warp-per-row, edge batching,
// fused BN1 stats. fp32 float4 gathers, unroll 8 for MLP.
// ---------------------------------------------------------------------------
__global__ void __launch_bounds__(256) spmm1_kernel(int Nn) {
    __shared__ float redS[8 * 256];
    __shared__ float redQ[8 * 256];
    const int tid = threadIdx.x;
    const int lane = tid & 31;
    const int wloc = tid >> 5;

    float bs[8], bq2[8];
#pragma unroll
    for (int k = 0; k < 8; k++) { bs[k] = 0.f; bq2[k] = 0.f; }

    for (int row = blockIdx.x * 8 + wloc; row < Nn; row += gridDim.x * 8) {
        int s = d_rowptr[row], e = d_rowptr[row + 1];
        float4 a0 = make_float4(0.f, 0.f, 0.f, 0.f);
        float4 a1 = make_float4(0.f, 0.f, 0.f, 0.f);
        for (int base = s; base < e; base += 32) {
            int take = min(32, e - base);
            int cc = 0; float vv = 0.f;
            if (lane < take) { cc = __ldcs(&d_cols[base + lane]); vv = __ldcs(&d_vals[base + lane]); }
            if (take == 32) {
#pragma unroll 8
                for (int j = 0; j < 32; j++) {
                    int c = __shfl_sync(0xffffffffu, cc, j);
                    float v = __shfl_sync(0xffffffffu, vv, j);
                    const float4* p = (const float4*)(d_xw1 + (size_t)c * F1);
                    float4 x0 = __ldg(&p[lane]);
                    float4 x1 = __ldg(&p[lane + 32]);
                    a0.x = fmaf(v, x0.x, a0.x); a0.y = fmaf(v, x0.y, a0.y);
                    a0.z = fmaf(v, x0.z, a0.z); a0.w = fmaf(v, x0.w, a0.w);
                    a1.x = fmaf(v, x1.x, a1.x); a1.y = fmaf(v, x1.y, a1.y);
                    a1.z = fmaf(v, x1.z, a1.z); a1.w = fmaf(v, x1.w, a1.w);
                }
            } else {
                for (int j = 0; j < take; j++) {
                    int c = __shfl_sync(0xffffffffu, cc, j);
                    float v = __shfl_sync(0xffffffffu, vv, j);
                    const float4* p = (const float4*)(d_xw1 + (size_t)c * F1);
                    float4 x0 = __ldg(&p[lane]);
                    float4 x1 = __ldg(&p[lane + 32]);
                    a0.x = fmaf(v, x0.x, a0.x); a0.y = fmaf(v, x0.y, a0.y);
                    a0.z = fmaf(v, x0.z, a0.z); a0.w = fmaf(v, x0.w, a0.w);
                    a1.x = fmaf(v, x1.x, a1.x); a1.y = fmaf(v, x1.y, a1.y);
                    a1.z = fmaf(v, x1.z, a1.z); a1.w = fmaf(v, x1.w, a1.w);
                }
            }
        }
        a0 = make_float4(fmaxf(a0.x, 0.f), fmaxf(a0.y, 0.f), fmaxf(a0.z, 0.f), fmaxf(a0.w, 0.f));
        a1 = make_float4(fmaxf(a1.x, 0.f), fmaxf(a1.y, 0.f), fmaxf(a1.z, 0.f), fmaxf(a1.w, 0.f));
        float4* o = (float4*)(d_h + (size_t)row * F1);
        __stcs(&o[lane], a0);
        __stcs(&o[lane + 32], a1);
        bs[0] += a0.x; bs[1] += a0.y; bs[2] += a0.z; bs[3] += a0.w;
        bs[4] += a1.x; bs[5] += a1.y; bs[6] += a1.z; bs[7] += a1.w;
        bq2[0] = fmaf(a0.x, a0.x, bq2[0]); bq2[1] = fmaf(a0.y, a0.y, bq2[1]);
        bq2[2] = fmaf(a0.z, a0.z, bq2[2]); bq2[3] = fmaf(a0.w, a0.w, bq2[3]);
        bq2[4] = fmaf(a1.x, a1.x, bq2[4]); bq2[5] = fmaf(a1.y, a1.y, bq2[5]);
        bq2[6] = fmaf(a1.z, a1.z, bq2[6]); bq2[7] = fmaf(a1.w, a1.w, bq2[7]);
    }
    // block reduction of BN1 partials (lane owns cols lane*4..+3 and 128+lane*4..+3)
    int base = wloc * 256 + lane * 8;
#pragma unroll
    for (int k = 0; k < 8; k++) { redS[base + k] = bs[k]; redQ[base + k] = bq2[k]; }
    __syncthreads();
    {
        int c = tid;                         // column 0..255
        int l = (c & 127) >> 2;
        int k = ((c >> 7) << 2) | (c & 3);
        float s = 0.f, q = 0.f;
#pragma unroll
        for (int w = 0; w < 8; w++) {
            s += redS[w * 256 + l * 8 + k];
            q += redQ[w * 256 + l * 8 + k];
        }
        atomicAdd(&d_sum1[c], s);
        atomicAdd(&d_sumsq1[c], q);
    }
}

// ---------------------------------------------------------------------------
// SpMM2 (persistent): out = relu(A_sparse @ hw2), fused BN2 stats.
// ---------------------------------------------------------------------------
__global__ void __launch_bounds__(256) spmm2_kernel(float* __restrict__ out, int Nn) {
    __shared__ float redS[8 * 64];
    __shared__ float redQ[8 * 64];
    const int tid = threadIdx.x;
    const int lane = tid & 31;
    const int wloc = tid >> 5;

    float bs0 = 0.f, bs1 = 0.f, bq0 = 0.f, bq1 = 0.f;

    for (int row = blockIdx.x * 8 + wloc; row < Nn; row += gridDim.x * 8) {
        int s = d_rowptr[row], e = d_rowptr[row + 1];
        float2 acc = make_float2(0.f, 0.f);
        for (int base = s; base < e; base += 32) {
            int take = min(32, e - base);
            int cc = 0; float vv = 0.f;
            if (lane < take) { cc = __ldcs(&d_cols[base + lane]); vv = __ldcs(&d_vals[base + lane]); }
            if (take == 32) {
#pragma unroll 8
                for (int j = 0; j < 32; j++) {
                    int c = __shfl_sync(0xffffffffu, cc, j);
                    float v = __shfl_sync(0xffffffffu, vv, j);
                    const float2* p = (const float2*)(d_hw2 + (size_t)c * F2);
                    float2 x0 = __ldg(&p[lane]);
                    acc.x = fmaf(v, x0.x, acc.x);
                    acc.y = fmaf(v, x0.y, acc.y);
                }
            } else {
                for (int j = 0; j < take; j++) {
                    int c = __shfl_sync(0xffffffffu, cc, j);
                    float v = __shfl_sync(0xffffffffu, vv, j);
                    const float2* p = (const float2*)(d_hw2 + (size_t)c * F2);
                    float2 x0 = __ldg(&p[lane]);
                    acc.x = fmaf(v, x0.x, acc.x);
                    acc.y = fmaf(v, x0.y, acc.y);
                }
            }
        }
        acc.x = fmaxf(acc.x, 0.f);
        acc.y = fmaxf(acc.y, 0.f);
        __stcs(&((float2*)(out + (size_t)row * F2))[lane], acc);
        bs0 += acc.x; bs1 += acc.y;
        bq0 = fmaf(acc.x, acc.x, bq0);
        bq1 = fmaf(acc.y, acc.y, bq1);
    }
    int base = wloc * 64 + lane * 2;
    redS[base] = bs0; redS[base + 1] = bs1;
    redQ[base] = bq0; redQ[base + 1] = bq1;
    __syncthreads();
    if (tid < 64) {
        float s = 0.f, q = 0.f;
#pragma unroll
        for (int w = 0; w < 8; w++) {
            s += redS[w * 64 + tid];
            q += redQ[w * 64 + tid];
        }
        atomicAdd(&d_sum2[tid], s);
        atomicAdd(&d_sumsq2[tid], q);
    }
}

// ---------------------------------------------------------------------------
// BN2 finalize + apply in one kernel (in place on d_out)
// ---------------------------------------------------------------------------
__global__ void bnapply2_kernel(float* __restrict__ out,
                                const float* __restrict__ g2,
                                const float* __restrict__ b2,
                                int Nn, int total4) {
    __shared__ float s_sc[F2], s_bi[F2];
    if (threadIdx.x < F2) {
        int c = threadIdx.x;
        float inv = 1.f / (float)Nn;
        float mean = d_sum2[c] * inv;
        float var = d_sumsq2[c] * inv - mean * mean;
        float rs = rsqrtf(var + 1e-5f);
        float sc = g2[c] * rs;
        s_sc[c] = sc;
        s_bi[c] = b2[c] - mean * sc;
    }
    __syncthreads();
    int i = blockIdx.x * blockDim.x + threadIdx.x;
    if (i < total4) {
        int c = (i * 4) & (F2 - 1);
        float4 v = ((float4*)out)[i];
        v.x = fmaf(v.x, s_sc[c + 0], s_bi[c + 0]);
        v.y = fmaf(v.y, s_sc[c + 1], s_bi[c + 1]);
        v.z = fmaf(v.z, s_sc[c + 2], s_bi[c + 2]);
        v.w = fmaf(v.w, s_sc[c + 3], s_bi[c + 3]);
        ((float4*)out)[i] = v;
    }
}

// ---------------------------------------------------------------------------
// Launch sequence: CSR build forked onto a side stream, joined before SpMM1.
// (Round-10 champion structure.)
// ---------------------------------------------------------------------------
extern "C" void kernel_launch(void* const* d_in, const int* in_sizes, int n_in,
                              void* d_out, int out_size) {
    const float* x    = (const float*)d_in[0];
    const int*   erow = (const int*)d_in[1];
    const int*   ecol = (const int*)d_in[2];
    const float* evl  = (const float*)d_in[3];
    const float* W1   = (const float*)d_in[4];
    const float* g1   = (const float*)d_in[5];
    const float* b1   = (const float*)d_in[6];
    const float* W2   = (const float*)d_in[7];
    const float* g2   = (const float*)d_in[8];
    const float* b2   = (const float*)d_in[9];
    float* out = (float*)d_out;

    const int Nn = in_sizes[0] / F0;   // 100000
    const int E  = in_sizes[1];        // 3200000
    const int nch = (Nn + 1023) / 1024;

    static cudaStream_t s2 = nullptr;
    static cudaEvent_t evFork = nullptr, evJoin = nullptr;
    static int attr_done = 0;
    if (!attr_done) {
        cudaFuncSetAttribute(gemm1_mma_kernel,
                             cudaFuncAttributeMaxDynamicSharedMemorySize, SMEM1);
        cudaFuncSetAttribute(gemm2_mma_kernel,
                             cudaFuncAttributeMaxDynamicSharedMemorySize, SMEM2);
        cudaStreamCreateWithFlags(&s2, cudaStreamNonBlocking);
        cudaEventCreateWithFlags(&evFork, cudaEventDisableTiming);
        cudaEventCreateWithFlags(&evJoin, cudaEventDisableTiming);
        attr_done = 1;
    }

    // ---- fork: CSR build on s2, GEMM1 path on main stream
    cudaEventRecord(evFork, 0);
    cudaStreamWaitEvent(s2, evFork, 0);

    zero_kernel<<<(Nn + 255) / 256, 256, 0, s2>>>(Nn);
    hist_kernel<<<(E + 255) / 256, 256, 0, s2>>>(erow, E);
    scanA_kernel<<<nch, 1024, 0, s2>>>(Nn);
    scanB_kernel<<<1, 128, 0, s2>>>(nch);
    scanC_kernel<<<(Nn + 255) / 256, 256, 0, s2>>>(Nn, E);
    scatter_kernel<<<(E + 255) / 256, 256, 0, s2>>>(erow, ecol, evl, E);
    cudaEventRecord(evJoin, s2);

    prepW1_kernel<<<(F0 * F1 + 255) / 256, 256>>>(W1);
    prepW2_kernel<<<(F1 * F2 + 255) / 256, 256>>>(W2);
    gemm1_mma_kernel<<<dim3((Nn + 127) / 128, 2), 256, SMEM1>>>(x, Nn);

    // ---- join
    cudaStreamWaitEvent(0, evJoin, 0);

    // Layer 1
    spmm1_kernel<<<1184, 256>>>(Nn);

    // Layer 2 (BN1 finalize fused into GEMM2; BN2 finalize fused into apply)
    gemm2_mma_kernel<<<(Nn + 127) / 128, 256, SMEM2>>>(g1, b1, Nn);
    spmm2_kernel<<<1184, 256>>>(out, Nn);
    bnapply2_kernel<<<(Nn * F2 / 4 + 255) / 256, 256>>>(out, g2, b2, Nn, Nn * F2 / 4);
}

// round 16
// speedup vs baseline: 1.0654x; 1.0654x over previous
#include <cuda_runtime.h>
#include <cuda_bf16.h>
#include <cuda_fp16.h>
#include <stdint.h>

// ---------------------------------------------------------------------------
// Problem constants
// ---------------------------------------------------------------------------
#define NMAX 100000
#define EMAX 3200000
#define F0 512
#define F1 256
#define F2 64

// ---------------------------------------------------------------------------
// Static device scratch
// ---------------------------------------------------------------------------
__device__ float d_xw1[NMAX * F1];
__device__ float d_h[NMAX * F1];
__device__ float d_hw2[NMAX * F2];
__device__ int   d_cnt[NMAX];
__device__ int   d_fill[NMAX];
__device__ int   d_rowptr[NMAX + 1];
__device__ int   d_cols[EMAX];
__device__ float d_vals[EMAX];
__device__ int   d_chunksums[128];
__device__ float d_sum1[F1], d_sumsq1[F1];
__device__ float d_sum2[F2], d_sumsq2[F2];
// W1 split: hi/lo fp16, layout [N=256][K=512] K-major
__device__ __align__(128) __half d_Bh[F1 * F0];
__device__ __align__(128) __half d_Bl[F1 * F0];
// W2 split: hi/lo fp16, layout [N=64][K=256] K-major
__device__ __align__(128) __half d_B2h[F2 * F1];
__device__ __align__(128) __half d_B2l[F2 * F1];

// ---------------------------------------------------------------------------
// Helpers
// ---------------------------------------------------------------------------
__device__ __forceinline__ uint32_t smem_u32(const void* p) {
    uint32_t a;
    asm("{ .reg .u64 t; cvta.to.shared.u64 t, %1; cvt.u32.u64 %0, t; }" : "=r"(a) : "l"(p));
    return a;
}
__device__ __forceinline__ uint32_t pack2hi_h(float a, float b) {
    __half2 t = __floats2half2_rn(a, b);
    return *(uint32_t*)&t;
}
__device__ __forceinline__ uint32_t pack2lo_h(float a, float b) {
    float ah = __half2float(__float2half_rn(a));
    float bh = __half2float(__float2half_rn(b));
    __half2 t = __floats2half2_rn(a - ah, b - bh);
    return *(uint32_t*)&t;
}
__device__ __forceinline__ void mma_f16(float* d, const uint32_t* a, uint32_t b0, uint32_t b1) {
    asm volatile(
        "mma.sync.aligned.m16n8k16.row.col.f32.f16.f16.f32 "
        "{%0,%1,%2,%3}, {%4,%5,%6,%7}, {%8,%9}, {%0,%1,%2,%3};"
        : "+f"(d[0]), "+f"(d[1]), "+f"(d[2]), "+f"(d[3])
        : "r"(a[0]), "r"(a[1]), "r"(a[2]), "r"(a[3]), "r"(b0), "r"(b1));
}
__device__ __forceinline__ void ldmatrix_x4(uint32_t* r, uint32_t addr) {
    asm volatile("ldmatrix.sync.aligned.m8n8.x4.shared.b16 {%0,%1,%2,%3}, [%4];"
                 : "=r"(r[0]), "=r"(r[1]), "=r"(r[2]), "=r"(r[3]) : "r"(addr));
}
__device__ __forceinline__ void cp_async16(uint32_t saddr, const void* gptr) {
    asm volatile("cp.async.ca.shared.global [%0], [%1], 16;" :: "r"(saddr), "l"(gptr));
}
__device__ __forceinline__ void cp_commit() {
    asm volatile("cp.async.commit_group;" ::: "memory");
}
__device__ __forceinline__ void cp_wait0() {
    asm volatile("cp.async.wait_group 0;" ::: "memory");
}

// ---------------------------------------------------------------------------
// Zero transient accumulators
// ---------------------------------------------------------------------------
__global__ void zero_kernel(int Nn) {
    int i = blockIdx.x * blockDim.x + threadIdx.x;
    if (i < Nn) { d_cnt[i] = 0; d_fill[i] = 0; }
    if (i < F1) { d_sum1[i] = 0.f; d_sumsq1[i] = 0.f; }
    if (i < F2) { d_sum2[i] = 0.f; d_sumsq2[i] = 0.f; }
}

// ---------------------------------------------------------------------------
// CSR build
// ---------------------------------------------------------------------------
__global__ void hist_kernel(const int* __restrict__ erow, int E) {
    int i = blockIdx.x * blockDim.x + threadIdx.x;
    if (i < E) atomicAdd(&d_cnt[erow[i]], 1);
}

__global__ void scanA_kernel(int Nn) {
    __shared__ int sh[1024];
    int gid = blockIdx.x * 1024 + threadIdx.x;
    int v = (gid < Nn) ? d_cnt[gid] : 0;
    sh[threadIdx.x] = v;
    __syncthreads();
#pragma unroll
    for (int off = 1; off < 1024; off <<= 1) {
        int t = (threadIdx.x >= off) ? sh[threadIdx.x - off] : 0;
        __syncthreads();
        sh[threadIdx.x] += t;
        __syncthreads();
    }
    if (gid < Nn) d_rowptr[gid] = sh[threadIdx.x] - v;
    if (threadIdx.x == 1023) d_chunksums[blockIdx.x] = sh[1023];
}

__global__ void scanB_kernel(int nch) {
    __shared__ int sh[128];
    int v = (threadIdx.x < nch) ? d_chunksums[threadIdx.x] : 0;
    sh[threadIdx.x] = v;
    __syncthreads();
#pragma unroll
    for (int off = 1; off < 128; off <<= 1) {
        int t = (threadIdx.x >= off) ? sh[threadIdx.x - off] : 0;
        __syncthreads();
        sh[threadIdx.x] += t;
        __syncthreads();
    }
    if (threadIdx.x < nch) d_chunksums[threadIdx.x] = sh[threadIdx.x] - v;
}

__global__ void scanC_kernel(int Nn, int E) {
    int gid = blockIdx.x * blockDim.x + threadIdx.x;
    if (gid < Nn) d_rowptr[gid] += d_chunksums[gid >> 10];
    if (gid == 0) d_rowptr[Nn] = E;
}

__global__ void scatter_kernel(const int* __restrict__ erow,
                               const int* __restrict__ ecol,
                               const float* __restrict__ eval, int E) {
    int i = blockIdx.x * blockDim.x + threadIdx.x;
    if (i < E) {
        int r = erow[i];
        int p = d_rowptr[r] + atomicAdd(&d_fill[r], 1);
        d_cols[p] = ecol[i];
        d_vals[p] = eval[i];
    }
}

// ---------------------------------------------------------------------------
// Weight prep: split W into fp16 hi + lo, transposed to K-major
// ---------------------------------------------------------------------------
__global__ void prepW1_kernel(const float* __restrict__ W1) {
    int i = blockIdx.x * blockDim.x + threadIdx.x;
    if (i >= F0 * F1) return;
    int k = i >> 8;
    int n = i & 255;
    float w = W1[i];
    __half h = __float2half_rn(w);
    __half l = __float2half_rn(w - __half2float(h));
    d_Bh[(size_t)n * F0 + k] = h;
    d_Bl[(size_t)n * F0 + k] = l;
}
__global__ void prepW2_kernel(const float* __restrict__ W2) {
    int i = blockIdx.x * blockDim.x + threadIdx.x;
    if (i >= F1 * F2) return;
    int k = i >> 6;
    int n = i & 63;
    float w = W2[i];
    __half h = __float2half_rn(w);
    __half l = __float2half_rn(w - __half2float(h));
    d_B2h[(size_t)n * F1 + k] = h;
    d_B2l[(size_t)n * F1 + k] = l;
}

// ---------------------------------------------------------------------------
// GEMM1 via mma.sync fp16 3-term: Ahi*Bhi + Alo*Bhi + Ahi*Blo
// Block tile 128x128; warp tile 32x64 (4x2 warps); 16 k-blocks of 32 fp32 cols.
// Buffer: A_hi 0 | A_lo 10240 | B_hi 20480 | B_lo 30720. Double-buffered.
// ---------------------------------------------------------------------------
#define PITCHB 80
#define BUFS1 40960
#define SMEM1 (2 * BUFS1)
#define KBLK1 16

__global__ void __launch_bounds__(256, 2)
gemm1_mma_kernel(const float* __restrict__ x, int M) {
    extern __shared__ __align__(16) char sm[];
    const int tid = threadIdx.x;
    const int wid = tid >> 5;
    const int lane = tid & 31;
    const int warp_m = wid & 3;
    const int warp_n = wid >> 2;
    const int gid = lane >> 2;
    const int tg = lane & 3;
    const int bm0 = blockIdx.x * 128;
    const int bn0 = blockIdx.y * 128;
    const uint32_t sb = smem_u32(sm);

    float acc[2][8][4];
#pragma unroll
    for (int mt = 0; mt < 2; mt++)
#pragma unroll
        for (int nt = 0; nt < 8; nt++)
#pragma unroll
            for (int q = 0; q < 4; q++) acc[mt][nt][q] = 0.f;

    const int arow = tid >> 3;
    const int af4 = tid & 7;
    const int brow = tid >> 2;
    const int bq = tid & 3;

    // ---- prologue: k-block 0
    {
#pragma unroll
        for (int i = 0; i < 4; i++) {
            int row = arow + i * 32;
            int rg = bm0 + row;
            float4 f = make_float4(0.f, 0.f, 0.f, 0.f);
            if (rg < M) f = *(const float4*)(x + (size_t)rg * F0 + af4 * 4);
            *(uint2*)(sm + row * PITCHB + af4 * 8) =
                make_uint2(pack2hi_h(f.x, f.y), pack2hi_h(f.z, f.w));
            *(uint2*)(sm + 10240 + row * PITCHB + af4 * 8) =
                make_uint2(pack2lo_h(f.x, f.y), pack2lo_h(f.z, f.w));
        }
#pragma unroll
        for (int i = 0; i < 2; i++) {
            int row = brow + i * 64;
            cp_async16(sb + 20480 + row * PITCHB + bq * 16,
                       d_Bh + (size_t)(bn0 + row) * F0 + bq * 8);
            cp_async16(sb + 30720 + row * PITCHB + bq * 16,
                       d_Bl + (size_t)(bn0 + row) * F0 + bq * 8);
        }
        cp_commit();
        cp_wait0();
        __syncthreads();
    }

    for (int c = 0; c < KBLK1; c++) {
        const int buf = c & 1;
        float4 fa[4];
        const bool have = (c + 1 < KBLK1);
        if (have) {
            const int sk0 = (c + 1) * 32;
#pragma unroll
            for (int i = 0; i < 4; i++) {
                int row = arow + i * 32;
                int rg = bm0 + row;
                fa[i] = make_float4(0.f, 0.f, 0.f, 0.f);
                if (rg < M) fa[i] = *(const float4*)(x + (size_t)rg * F0 + sk0 + af4 * 4);
            }
            const uint32_t bb = sb + (buf ^ 1) * BUFS1;
#pragma unroll
            for (int i = 0; i < 2; i++) {
                int row = brow + i * 64;
                cp_async16(bb + 20480 + row * PITCHB + bq * 16,
                           d_Bh + (size_t)(bn0 + row) * F0 + sk0 + bq * 8);
                cp_async16(bb + 30720 + row * PITCHB + bq * 16,
                           d_Bl + (size_t)(bn0 + row) * F0 + sk0 + bq * 8);
            }
            cp_commit();
        }
        // ---- compute on buf
        const uint32_t sA = sb + buf * BUFS1;
        const char* Bh = sm + buf * BUFS1 + 20480;
        const char* Bl = sm + buf * BUFS1 + 30720;
#pragma unroll
        for (int ks = 0; ks < 2; ks++) {
            uint32_t ahi[2][4], alo[2][4];
#pragma unroll
            for (int mt = 0; mt < 2; mt++) {
                uint32_t rowoff = (warp_m * 32 + mt * 16 + (lane & 15)) * PITCHB
                                  + ks * 32 + (lane >> 4) * 16;
                ldmatrix_x4(ahi[mt], sA + rowoff);
                ldmatrix_x4(alo[mt], sA + 10240 + rowoff);
            }
#pragma unroll
            for (int nt = 0; nt < 8; nt++) {
                uint32_t roff = (warp_n * 64 + nt * 8 + gid) * PITCHB + ks * 32 + tg * 4;
                uint32_t bh0 = *(const uint32_t*)(Bh + roff);
                uint32_t bh1 = *(const uint32_t*)(Bh + roff + 16);
                uint32_t bl0 = *(const uint32_t*)(Bl + roff);
                uint32_t bl1 = *(const uint32_t*)(Bl + roff + 16);
                mma_f16(acc[0][nt], ahi[0], bh0, bh1);
                mma_f16(acc[1][nt], ahi[1], bh0, bh1);
                mma_f16(acc[0][nt], alo[0], bh0, bh1);
                mma_f16(acc[1][nt], alo[1], bh0, bh1);
                mma_f16(acc[0][nt], ahi[0], bl0, bl1);
                mma_f16(acc[1][nt], ahi[1], bl0, bl1);
            }
        }
        if (have) {
            char* dA = sm + (buf ^ 1) * BUFS1;
#pragma unroll
            for (int i = 0; i < 4; i++) {
                int row = arow + i * 32;
                *(uint2*)(dA + row * PITCHB + af4 * 8) =
                    make_uint2(pack2hi_h(fa[i].x, fa[i].y), pack2hi_h(fa[i].z, fa[i].w));
                *(uint2*)(dA + 10240 + row * PITCHB + af4 * 8) =
                    make_uint2(pack2lo_h(fa[i].x, fa[i].y), pack2lo_h(fa[i].z, fa[i].w));
            }
        }
        cp_wait0();
        __syncthreads();
    }

    // ---- epilogue: write fp32 result
#pragma unroll
    for (int mt = 0; mt < 2; mt++) {
        int r0 = bm0 + warp_m * 32 + mt * 16 + gid;
        int r1 = r0 + 8;
#pragma unroll
        for (int nt = 0; nt < 8; nt++) {
            int col = bn0 + warp_n * 64 + nt * 8 + tg * 2;
            if (r0 < M)
                *(float2*)(d_xw1 + (size_t)r0 * F1 + col) =
                    make_float2(acc[mt][nt][0], acc[mt][nt][1]);
            if (r1 < M)
                *(float2*)(d_xw1 + (size_t)r1 * F1 + col) =
                    make_float2(acc[mt][nt][2], acc[mt][nt][3]);
        }
    }
}

// ---------------------------------------------------------------------------
// GEMM2 via mma.sync fp16 3-term: hw2 = relu(bn1(h)) @ W2
// BN1 finalize fused at kernel start.
// ---------------------------------------------------------------------------
#define BUFS2 30720
#define SMEM2 (2 * BUFS2)
#define KBLK2 8

__global__ void __launch_bounds__(256, 2)
gemm2_mma_kernel(const float* __restrict__ g1, const float* __restrict__ b1, int M) {
    extern __shared__ __align__(16) char sm[];
    __shared__ float s_sc[F1], s_bi[F1];
    const int tid = threadIdx.x;
    const int wid = tid >> 5;
    const int lane = tid & 31;
    const int gid = lane >> 2;
    const int tg = lane & 3;
    const int bm0 = blockIdx.x * 128;
    const uint32_t sb = smem_u32(sm);

    // fused BN1 finalize
    {
        float inv = 1.f / (float)M;
        float mean = d_sum1[tid] * inv;
        float var = d_sumsq1[tid] * inv - mean * mean;
        float rs = rsqrtf(var + 1e-5f);
        float sc = g1[tid] * rs;
        s_sc[tid] = sc;
        s_bi[tid] = b1[tid] - mean * sc;
    }
    __syncthreads();

    float acc[8][4];
#pragma unroll
    for (int nt = 0; nt < 8; nt++)
#pragma unroll
        for (int q = 0; q < 4; q++) acc[nt][q] = 0.f;

    const int arow = tid >> 3;
    const int af4 = tid & 7;
    const int brow = tid >> 2;
    const int bq = tid & 3;

    auto packA = [&](char* dst, int sk0) {
#pragma unroll
        for (int i = 0; i < 4; i++) {
            int row = arow + i * 32;
            int rg = bm0 + row;
            float4 f = make_float4(0.f, 0.f, 0.f, 0.f);
            if (rg < M) {
                f = __ldcs((const float4*)(d_h + (size_t)rg * F1 + sk0 + af4 * 4));
                int cb = sk0 + af4 * 4;
                f.x = fmaxf(fmaf(f.x, s_sc[cb + 0], s_bi[cb + 0]), 0.f);
                f.y = fmaxf(fmaf(f.y, s_sc[cb + 1], s_bi[cb + 1]), 0.f);
                f.z = fmaxf(fmaf(f.z, s_sc[cb + 2], s_bi[cb + 2]), 0.f);
                f.w = fmaxf(fmaf(f.w, s_sc[cb + 3], s_bi[cb + 3]), 0.f);
            }
            *(uint2*)(dst + row * PITCHB + af4 * 8) =
                make_uint2(pack2hi_h(f.x, f.y), pack2hi_h(f.z, f.w));
            *(uint2*)(dst + 10240 + row * PITCHB + af4 * 8) =
                make_uint2(pack2lo_h(f.x, f.y), pack2lo_h(f.z, f.w));
        }
    };

    packA(sm, 0);
    cp_async16(sb + 20480 + brow * PITCHB + bq * 16, d_B2h + (size_t)brow * F1 + bq * 8);
    cp_async16(sb + 25600 + brow * PITCHB + bq * 16, d_B2l + (size_t)brow * F1 + bq * 8);
    cp_commit();
    cp_wait0();
    __syncthreads();

    for (int c = 0; c < KBLK2; c++) {
        const int buf = c & 1;
        const bool have = (c + 1 < KBLK2);
        if (have) {
            const int sk0 = (c + 1) * 32;
            const uint32_t bb = sb + (buf ^ 1) * BUFS2;
            cp_async16(bb + 20480 + brow * PITCHB + bq * 16,
                       d_B2h + (size_t)brow * F1 + sk0 + bq * 8);
            cp_async16(bb + 25600 + brow * PITCHB + bq * 16,
                       d_B2l + (size_t)brow * F1 + sk0 + bq * 8);
            cp_commit();
        }
        const uint32_t sA = sb + buf * BUFS2;
        const char* Bh = sm + buf * BUFS2 + 20480;
        const char* Bl = sm + buf * BUFS2 + 25600;
#pragma unroll
        for (int ks = 0; ks < 2; ks++) {
            uint32_t ahi[4], alo[4];
            uint32_t rowoff = (wid * 16 + (lane & 15)) * PITCHB + ks * 32 + (lane >> 4) * 16;
            ldmatrix_x4(ahi, sA + rowoff);
            ldmatrix_x4(alo, sA + 10240 + rowoff);
#pragma unroll
            for (int nt = 0; nt < 8; nt++) {
                uint32_t roff = (nt * 8 + gid) * PITCHB + ks * 32 + tg * 4;
                uint32_t bh0 = *(const uint32_t*)(Bh + roff);
                uint32_t bh1 = *(const uint32_t*)(Bh + roff + 16);
                uint32_t bl0 = *(const uint32_t*)(Bl + roff);
                uint32_t bl1 = *(const uint32_t*)(Bl + roff + 16);
                mma_f16(acc[nt], ahi, bh0, bh1);
                mma_f16(acc[nt], alo, bh0, bh1);
                mma_f16(acc[nt], ahi, bl0, bl1);
            }
        }
        if (have) packA(sm + (buf ^ 1) * BUFS2, (c + 1) * 32);
        cp_wait0();
        __syncthreads();
    }

    // ---- epilogue
    int r0 = bm0 + wid * 16 + gid;
    int r1 = r0 + 8;
#pragma unroll
    for (int nt = 0; nt < 8; nt++) {
        int col = nt * 8 + tg * 2;
        if (r0 < M)
            *(float2*)(d_hw2 + (size_t)r0 * F2 + col) = make_float2(acc[nt][0], acc[nt][1]);
        if (r1 < M)
            *(float2*)(d_hw2 + (size_t)r1 * F2 + col) = make_float2(acc[nt][2], acc[nt][3]);
    }
}

// ---------------------------------------------------------------------------
// SpMM1 (persistent): h = relu(A_sparse @ xw1), warp-per-row, edge batching,
// fused BN1 stats. fp32 float4 gathers, unroll 4 (measured optimum).
// ---------------------------------------------------------------------------
__global__ void __launch_bounds__(256) spmm1_kernel(int Nn) {
    __shared__ float redS[8 * 256];
    __shared__ float redQ[8 * 256];
    const int tid = threadIdx.x;
    const int lane = tid & 31;
    const int wloc = tid >> 5;

    float bs[8], bq2[8];
#pragma unroll
    for (int k = 0; k < 8; k++) { bs[k] = 0.f; bq2[k] = 0.f; }

    for (int row = blockIdx.x * 8 + wloc; row < Nn; row += gridDim.x * 8) {
        int s = d_rowptr[row], e = d_rowptr[row + 1];
        float4 a0 = make_float4(0.f, 0.f, 0.f, 0.f);
        float4 a1 = make_float4(0.f, 0.f, 0.f, 0.f);
        for (int base = s; base < e; base += 32) {
            int take = min(32, e - base);
            int cc = 0; float vv = 0.f;
            if (lane < take) { cc = __ldcs(&d_cols[base + lane]); vv = __ldcs(&d_vals[base + lane]); }
            if (take == 32) {
#pragma unroll 4
                for (int j = 0; j < 32; j++) {
                    int c = __shfl_sync(0xffffffffu, cc, j);
                    float v = __shfl_sync(0xffffffffu, vv, j);
                    const float4* p = (const float4*)(d_xw1 + (size_t)c * F1);
                    float4 x0 = __ldg(&p[lane]);
                    float4 x1 = __ldg(&p[lane + 32]);
                    a0.x = fmaf(v, x0.x, a0.x); a0.y = fmaf(v, x0.y, a0.y);
                    a0.z = fmaf(v, x0.z, a0.z); a0.w = fmaf(v, x0.w, a0.w);
                    a1.x = fmaf(v, x1.x, a1.x); a1.y = fmaf(v, x1.y, a1.y);
                    a1.z = fmaf(v, x1.z, a1.z); a1.w = fmaf(v, x1.w, a1.w);
                }
            } else {
                for (int j = 0; j < take; j++) {
                    int c = __shfl_sync(0xffffffffu, cc, j);
                    float v = __shfl_sync(0xffffffffu, vv, j);
                    const float4* p = (const float4*)(d_xw1 + (size_t)c * F1);
                    float4 x0 = __ldg(&p[lane]);
                    float4 x1 = __ldg(&p[lane + 32]);
                    a0.x = fmaf(v, x0.x, a0.x); a0.y = fmaf(v, x0.y, a0.y);
                    a0.z = fmaf(v, x0.z, a0.z); a0.w = fmaf(v, x0.w, a0.w);
                    a1.x = fmaf(v, x1.x, a1.x); a1.y = fmaf(v, x1.y, a1.y);
                    a1.z = fmaf(v, x1.z, a1.z); a1.w = fmaf(v, x1.w, a1.w);
                }
            }
        }
        a0 = make_float4(fmaxf(a0.x, 0.f), fmaxf(a0.y, 0.f), fmaxf(a0.z, 0.f), fmaxf(a0.w, 0.f));
        a1 = make_float4(fmaxf(a1.x, 0.f), fmaxf(a1.y, 0.f), fmaxf(a1.z, 0.f), fmaxf(a1.w, 0.f));
        float4* o = (float4*)(d_h + (size_t)row * F1);
        __stcs(&o[lane], a0);
        __stcs(&o[lane + 32], a1);
        bs[0] += a0.x; bs[1] += a0.y; bs[2] += a0.z; bs[3] += a0.w;
        bs[4] += a1.x; bs[5] += a1.y; bs[6] += a1.z; bs[7] += a1.w;
        bq2[0] = fmaf(a0.x, a0.x, bq2[0]); bq2[1] = fmaf(a0.y, a0.y, bq2[1]);
        bq2[2] = fmaf(a0.z, a0.z, bq2[2]); bq2[3] = fmaf(a0.w, a0.w, bq2[3]);
        bq2[4] = fmaf(a1.x, a1.x, bq2[4]); bq2[5] = fmaf(a1.y, a1.y, bq2[5]);
        bq2[6] = fmaf(a1.z, a1.z, bq2[6]); bq2[7] = fmaf(a1.w, a1.w, bq2[7]);
    }
    // block reduction of BN1 partials (lane owns cols lane*4..+3 and 128+lane*4..+3)
    int base = wloc * 256 + lane * 8;
#pragma unroll
    for (int k = 0; k < 8; k++) { redS[base + k] = bs[k]; redQ[base + k] = bq2[k]; }
    __syncthreads();
    {
        int c = tid;                         // column 0..255
        int l = (c & 127) >> 2;
        int k = ((c >> 7) << 2) | (c & 3);
        float s = 0.f, q = 0.f;
#pragma unroll
        for (int w = 0; w < 8; w++) {
            s += redS[w * 256 + l * 8 + k];
            q += redQ[w * 256 + l * 8 + k];
        }
        atomicAdd(&d_sum1[c], s);
        atomicAdd(&d_sumsq1[c], q);
    }
}

// ---------------------------------------------------------------------------
// SpMM2 (persistent): out = relu(A_sparse @ hw2), fused BN2 stats.
// ---------------------------------------------------------------------------
__global__ void __launch_bounds__(256) spmm2_kernel(float* __restrict__ out, int Nn) {
    __shared__ float redS[8 * 64];
    __shared__ float redQ[8 * 64];
    const int tid = threadIdx.x;
    const int lane = tid & 31;
    const int wloc = tid >> 5;

    float bs0 = 0.f, bs1 = 0.f, bq0 = 0.f, bq1 = 0.f;

    for (int row = blockIdx.x * 8 + wloc; row < Nn; row += gridDim.x * 8) {
        int s = d_rowptr[row], e = d_rowptr[row + 1];
        float2 acc = make_float2(0.f, 0.f);
        for (int base = s; base < e; base += 32) {
            int take = min(32, e - base);
            int cc = 0; float vv = 0.f;
            if (lane < take) { cc = __ldcs(&d_cols[base + lane]); vv = __ldcs(&d_vals[base + lane]); }
            if (take == 32) {
#pragma unroll 4
                for (int j = 0; j < 32; j++) {
                    int c = __shfl_sync(0xffffffffu, cc, j);
                    float v = __shfl_sync(0xffffffffu, vv, j);
                    const float2* p = (const float2*)(d_hw2 + (size_t)c * F2);
                    float2 x0 = __ldg(&p[lane]);
                    acc.x = fmaf(v, x0.x, acc.x);
                    acc.y = fmaf(v, x0.y, acc.y);
                }
            } else {
                for (int j = 0; j < take; j++) {
                    int c = __shfl_sync(0xffffffffu, cc, j);
                    float v = __shfl_sync(0xffffffffu, vv, j);
                    const float2* p = (const float2*)(d_hw2 + (size_t)c * F2);
                    float2 x0 = __ldg(&p[lane]);
                    acc.x = fmaf(v, x0.x, acc.x);
                    acc.y = fmaf(v, x0.y, acc.y);
                }
            }
        }
        acc.x = fmaxf(acc.x, 0.f);
        acc.y = fmaxf(acc.y, 0.f);
        __stcs(&((float2*)(out + (size_t)row * F2))[lane], acc);
        bs0 += acc.x; bs1 += acc.y;
        bq0 = fmaf(acc.x, acc.x, bq0);
        bq1 = fmaf(acc.y, acc.y, bq1);
    }
    int base = wloc * 64 + lane * 2;
    redS[base] = bs0; redS[base + 1] = bs1;
    redQ[base] = bq0; redQ[base + 1] = bq1;
    __syncthreads();
    if (tid < 64) {
        float s = 0.f, q = 0.f;
#pragma unroll
        for (int w = 0; w < 8; w++) {
            s += redS[w * 64 + tid];
            q += redQ[w * 64 + tid];
        }
        atomicAdd(&d_sum2[tid], s);
        atomicAdd(&d_sumsq2[tid], q);
    }
}

// ---------------------------------------------------------------------------
// BN2 finalize + apply in one kernel (in place on d_out)
// ---------------------------------------------------------------------------
__global__ void bnapply2_kernel(float* __restrict__ out,
                                const float* __restrict__ g2,
                                const float* __restrict__ b2,
                                int Nn, int total4) {
    __shared__ float s_sc[F2], s_bi[F2];
    if (threadIdx.x < F2) {
        int c = threadIdx.x;
        float inv = 1.f / (float)Nn;
        float mean = d_sum2[c] * inv;
        float var = d_sumsq2[c] * inv - mean * mean;
        float rs = rsqrtf(var + 1e-5f);
        float sc = g2[c] * rs;
        s_sc[c] = sc;
        s_bi[c] = b2[c] - mean * sc;
    }
    __syncthreads();
    int i = blockIdx.x * blockDim.x + threadIdx.x;
    if (i < total4) {
        int c = (i * 4) & (F2 - 1);
        float4 v = ((float4*)out)[i];
        v.x = fmaf(v.x, s_sc[c + 0], s_bi[c + 0]);
        v.y = fmaf(v.y, s_sc[c + 1], s_bi[c + 1]);
        v.z = fmaf(v.z, s_sc[c + 2], s_bi[c + 2]);
        v.w = fmaf(v.w, s_sc[c + 3], s_bi[c + 3]);
        ((float4*)out)[i] = v;
    }
}

// ---------------------------------------------------------------------------
// Launch sequence: CSR build forked onto a side stream, joined before SpMM1.
// (Round-10 champion structure, restored byte-exact.)
// ---------------------------------------------------------------------------
extern "C" void kernel_launch(void* const* d_in, const int* in_sizes, int n_in,
                              void* d_out, int out_size) {
    const float* x    = (const float*)d_in[0];
    const int*   erow = (const int*)d_in[1];
    const int*   ecol = (const int*)d_in[2];
    const float* evl  = (const float*)d_in[3];
    const float* W1   = (const float*)d_in[4];
    const float* g1   = (const float*)d_in[5];
    const float* b1   = (const float*)d_in[6];
    const float* W2   = (const float*)d_in[7];
    const float* g2   = (const float*)d_in[8];
    const float* b2   = (const float*)d_in[9];
    float* out = (float*)d_out;

    const int Nn = in_sizes[0] / F0;   // 100000
    const int E  = in_sizes[1];        // 3200000
    const int nch = (Nn + 1023) / 1024;

    static cudaStream_t s2 = nullptr;
    static cudaEvent_t evFork = nullptr, evJoin = nullptr;
    static int attr_done = 0;
    if (!attr_done) {
        cudaFuncSetAttribute(gemm1_mma_kernel,
                             cudaFuncAttributeMaxDynamicSharedMemorySize, SMEM1);
        cudaFuncSetAttribute(gemm2_mma_kernel,
                             cudaFuncAttributeMaxDynamicSharedMemorySize, SMEM2);
        cudaStreamCreateWithFlags(&s2, cudaStreamNonBlocking);
        cudaEventCreateWithFlags(&evFork, cudaEventDisableTiming);
        cudaEventCreateWithFlags(&evJoin, cudaEventDisableTiming);
        attr_done = 1;
    }

    // ---- fork: CSR build on s2, GEMM1 path on main stream
    cudaEventRecord(evFork, 0);
    cudaStreamWaitEvent(s2, evFork, 0);

    zero_kernel<<<(Nn + 255) / 256, 256, 0, s2>>>(Nn);
    hist_kernel<<<(E + 255) / 256, 256, 0, s2>>>(erow, E);
    scanA_kernel<<<nch, 1024, 0, s2>>>(Nn);
    scanB_kernel<<<1, 128, 0, s2>>>(nch);
    scanC_kernel<<<(Nn + 255) / 256, 256, 0, s2>>>(Nn, E);
    scatter_kernel<<<(E + 255) / 256, 256, 0, s2>>>(erow, ecol, evl, E);
    cudaEventRecord(evJoin, s2);

    prepW1_kernel<<<(F0 * F1 + 255) / 256, 256>>>(W1);
    prepW2_kernel<<<(F1 * F2 + 255) / 256, 256>>>(W2);
    gemm1_mma_kernel<<<dim3((Nn + 127) / 128, 2), 256, SMEM1>>>(x, Nn);

    // ---- join
    cudaStreamWaitEvent(0, evJoin, 0);

    // Layer 1
    spmm1_kernel<<<1184, 256>>>(Nn);

    // Layer 2 (BN1 finalize fused into GEMM2; BN2 finalize fused into apply)
    gemm2_mma_kernel<<<(Nn + 127) / 128, 256, SMEM2>>>(g1, b1, Nn);
    spmm2_kernel<<<1184, 256>>>(out, Nn);
    bnapply2_kernel<<<(Nn * F2 / 4 + 255) / 256, 256>>>(out, g2, b2, Nn, Nn * F2 / 4);
}

// round 17
// speedup vs baseline: 1.0736x; 1.0077x over previous
#include <cuda_runtime.h>
#include <cuda_bf16.h>
#include <cuda_fp16.h>
#include <stdint.h>

// ---------------------------------------------------------------------------
// Problem constants
// ---------------------------------------------------------------------------
#define NMAX 100000
#define EMAX 3200000
#define F0 512
#define F1 256
#define F2 64

// ---------------------------------------------------------------------------
// Static device scratch
// ---------------------------------------------------------------------------
__device__ float d_xw1[NMAX * F1];
__device__ float d_h[NMAX * F1];
__device__ float d_hw2[NMAX * F2];
__device__ int   d_cnt[NMAX];
__device__ int   d_fill[NMAX];
__device__ int   d_rowptr[NMAX + 1];
__device__ int   d_cols[EMAX];
__device__ float d_vals[EMAX];
__device__ int   d_chunksums[128];
__device__ float d_sum1[F1], d_sumsq1[F1];
__device__ float d_sum2[F2], d_sumsq2[F2];
// W1 split: hi/lo fp16, layout [N=256][K=512] K-major
__device__ __align__(128) __half d_Bh[F1 * F0];
__device__ __align__(128) __half d_Bl[F1 * F0];
// W2 split: hi/lo fp16, layout [N=64][K=256] K-major
__device__ __align__(128) __half d_B2h[F2 * F1];
__device__ __align__(128) __half d_B2l[F2 * F1];

// ---------------------------------------------------------------------------
// Helpers
// ---------------------------------------------------------------------------
__device__ __forceinline__ uint32_t smem_u32(const void* p) {
    uint32_t a;
    asm("{ .reg .u64 t; cvta.to.shared.u64 t, %1; cvt.u32.u64 %0, t; }" : "=r"(a) : "l"(p));
    return a;
}
__device__ __forceinline__ uint32_t pack2hi_h(float a, float b) {
    __half2 t = __floats2half2_rn(a, b);
    return *(uint32_t*)&t;
}
__device__ __forceinline__ uint32_t pack2lo_h(float a, float b) {
    float ah = __half2float(__float2half_rn(a));
    float bh = __half2float(__float2half_rn(b));
    __half2 t = __floats2half2_rn(a - ah, b - bh);
    return *(uint32_t*)&t;
}
__device__ __forceinline__ void mma_f16(float* d, const uint32_t* a, uint32_t b0, uint32_t b1) {
    asm volatile(
        "mma.sync.aligned.m16n8k16.row.col.f32.f16.f16.f32 "
        "{%0,%1,%2,%3}, {%4,%5,%6,%7}, {%8,%9}, {%0,%1,%2,%3};"
        : "+f"(d[0]), "+f"(d[1]), "+f"(d[2]), "+f"(d[3])
        : "r"(a[0]), "r"(a[1]), "r"(a[2]), "r"(a[3]), "r"(b0), "r"(b1));
}
__device__ __forceinline__ void ldmatrix_x4(uint32_t* r, uint32_t addr) {
    asm volatile("ldmatrix.sync.aligned.m8n8.x4.shared.b16 {%0,%1,%2,%3}, [%4];"
                 : "=r"(r[0]), "=r"(r[1]), "=r"(r[2]), "=r"(r[3]) : "r"(addr));
}
__device__ __forceinline__ void cp_async16(uint32_t saddr, const void* gptr) {
    asm volatile("cp.async.ca.shared.global [%0], [%1], 16;" :: "r"(saddr), "l"(gptr));
}
__device__ __forceinline__ void cp_commit() {
    asm volatile("cp.async.commit_group;" ::: "memory");
}
__device__ __forceinline__ void cp_wait0() {
    asm volatile("cp.async.wait_group 0;" ::: "memory");
}

// ---------------------------------------------------------------------------
// Zero transient accumulators
// ---------------------------------------------------------------------------
__global__ void zero_kernel(int Nn) {
    int i = blockIdx.x * blockDim.x + threadIdx.x;
    if (i < Nn) { d_cnt[i] = 0; d_fill[i] = 0; }
    if (i < F1) { d_sum1[i] = 0.f; d_sumsq1[i] = 0.f; }
    if (i < F2) { d_sum2[i] = 0.f; d_sumsq2[i] = 0.f; }
}

// ---------------------------------------------------------------------------
// CSR build
// ---------------------------------------------------------------------------
__global__ void hist_kernel(const int* __restrict__ erow, int E) {
    int i = blockIdx.x * blockDim.x + threadIdx.x;
    if (i < E) atomicAdd(&d_cnt[erow[i]], 1);
}

__global__ void scanA_kernel(int Nn) {
    __shared__ int sh[1024];
    int gid = blockIdx.x * 1024 + threadIdx.x;
    int v = (gid < Nn) ? d_cnt[gid] : 0;
    sh[threadIdx.x] = v;
    __syncthreads();
#pragma unroll
    for (int off = 1; off < 1024; off <<= 1) {
        int t = (threadIdx.x >= off) ? sh[threadIdx.x - off] : 0;
        __syncthreads();
        sh[threadIdx.x] += t;
        __syncthreads();
    }
    if (gid < Nn) d_rowptr[gid] = sh[threadIdx.x] - v;
    if (threadIdx.x == 1023) d_chunksums[blockIdx.x] = sh[1023];
}

__global__ void scanB_kernel(int nch) {
    __shared__ int sh[128];
    int v = (threadIdx.x < nch) ? d_chunksums[threadIdx.x] : 0;
    sh[threadIdx.x] = v;
    __syncthreads();
#pragma unroll
    for (int off = 1; off < 128; off <<= 1) {
        int t = (threadIdx.x >= off) ? sh[threadIdx.x - off] : 0;
        __syncthreads();
        sh[threadIdx.x] += t;
        __syncthreads();
    }
    if (threadIdx.x < nch) d_chunksums[threadIdx.x] = sh[threadIdx.x] - v;
}

__global__ void scanC_kernel(int Nn, int E) {
    int gid = blockIdx.x * blockDim.x + threadIdx.x;
    if (gid < Nn) d_rowptr[gid] += d_chunksums[gid >> 10];
    if (gid == 0) d_rowptr[Nn] = E;
}

__global__ void scatter_kernel(const int* __restrict__ erow,
                               const int* __restrict__ ecol,
                               const float* __restrict__ eval, int E) {
    int i = blockIdx.x * blockDim.x + threadIdx.x;
    if (i < E) {
        int r = erow[i];
        int p = d_rowptr[r] + atomicAdd(&d_fill[r], 1);
        d_cols[p] = ecol[i];
        d_vals[p] = eval[i];
    }
}

// ---------------------------------------------------------------------------
// Weight prep: split W into fp16 hi + lo, transposed to K-major
// ---------------------------------------------------------------------------
__global__ void prepW1_kernel(const float* __restrict__ W1) {
    int i = blockIdx.x * blockDim.x + threadIdx.x;
    if (i >= F0 * F1) return;
    int k = i >> 8;
    int n = i & 255;
    float w = W1[i];
    __half h = __float2half_rn(w);
    __half l = __float2half_rn(w - __half2float(h));
    d_Bh[(size_t)n * F0 + k] = h;
    d_Bl[(size_t)n * F0 + k] = l;
}
__global__ void prepW2_kernel(const float* __restrict__ W2) {
    int i = blockIdx.x * blockDim.x + threadIdx.x;
    if (i >= F1 * F2) return;
    int k = i >> 6;
    int n = i & 63;
    float w = W2[i];
    __half h = __float2half_rn(w);
    __half l = __float2half_rn(w - __half2float(h));
    d_B2h[(size_t)n * F1 + k] = h;
    d_B2l[(size_t)n * F1 + k] = l;
}

// ---------------------------------------------------------------------------
// GEMM1 via mma.sync fp16 3-term: Ahi*Bhi + Alo*Bhi + Ahi*Blo
// Block tile 128x128; warp tile 32x64 (4x2 warps); 16 k-blocks of 32 fp32 cols.
// Buffer: A_hi 0 | A_lo 10240 | B_hi 20480 | B_lo 30720. Double-buffered.
// ---------------------------------------------------------------------------
#define PITCHB 80
#define BUFS1 40960
#define SMEM1 (2 * BUFS1)
#define KBLK1 16

__global__ void __launch_bounds__(256, 2)
gemm1_mma_kernel(const float* __restrict__ x, int M) {
    extern __shared__ __align__(16) char sm[];
    const int tid = threadIdx.x;
    const int wid = tid >> 5;
    const int lane = tid & 31;
    const int warp_m = wid & 3;
    const int warp_n = wid >> 2;
    const int gid = lane >> 2;
    const int tg = lane & 3;
    const int bm0 = blockIdx.x * 128;
    const int bn0 = blockIdx.y * 128;
    const uint32_t sb = smem_u32(sm);

    float acc[2][8][4];
#pragma unroll
    for (int mt = 0; mt < 2; mt++)
#pragma unroll
        for (int nt = 0; nt < 8; nt++)
#pragma unroll
            for (int q = 0; q < 4; q++) acc[mt][nt][q] = 0.f;

    const int arow = tid >> 3;
    const int af4 = tid & 7;
    const int brow = tid >> 2;
    const int bq = tid & 3;

    // ---- prologue: k-block 0
    {
#pragma unroll
        for (int i = 0; i < 4; i++) {
            int row = arow + i * 32;
            int rg = bm0 + row;
            float4 f = make_float4(0.f, 0.f, 0.f, 0.f);
            if (rg < M) f = *(const float4*)(x + (size_t)rg * F0 + af4 * 4);
            *(uint2*)(sm + row * PITCHB + af4 * 8) =
                make_uint2(pack2hi_h(f.x, f.y), pack2hi_h(f.z, f.w));
            *(uint2*)(sm + 10240 + row * PITCHB + af4 * 8) =
                make_uint2(pack2lo_h(f.x, f.y), pack2lo_h(f.z, f.w));
        }
#pragma unroll
        for (int i = 0; i < 2; i++) {
            int row = brow + i * 64;
            cp_async16(sb + 20480 + row * PITCHB + bq * 16,
                       d_Bh + (size_t)(bn0 + row) * F0 + bq * 8);
            cp_async16(sb + 30720 + row * PITCHB + bq * 16,
                       d_Bl + (size_t)(bn0 + row) * F0 + bq * 8);
        }
        cp_commit();
        cp_wait0();
        __syncthreads();
    }

    for (int c = 0; c < KBLK1; c++) {
        const int buf = c & 1;
        float4 fa[4];
        const bool have = (c + 1 < KBLK1);
        if (have) {
            const int sk0 = (c + 1) * 32;
#pragma unroll
            for (int i = 0; i < 4; i++) {
                int row = arow + i * 32;
                int rg = bm0 + row;
                fa[i] = make_float4(0.f, 0.f, 0.f, 0.f);
                if (rg < M) fa[i] = *(const float4*)(x + (size_t)rg * F0 + sk0 + af4 * 4);
            }
            const uint32_t bb = sb + (buf ^ 1) * BUFS1;
#pragma unroll
            for (int i = 0; i < 2; i++) {
                int row = brow + i * 64;
                cp_async16(bb + 20480 + row * PITCHB + bq * 16,
                           d_Bh + (size_t)(bn0 + row) * F0 + sk0 + bq * 8);
                cp_async16(bb + 30720 + row * PITCHB + bq * 16,
                           d_Bl + (size_t)(bn0 + row) * F0 + sk0 + bq * 8);
            }
            cp_commit();
        }
        // ---- compute on buf
        const uint32_t sA = sb + buf * BUFS1;
        const char* Bh = sm + buf * BUFS1 + 20480;
        const char* Bl = sm + buf * BUFS1 + 30720;
#pragma unroll
        for (int ks = 0; ks < 2; ks++) {
            uint32_t ahi[2][4], alo[2][4];
#pragma unroll
            for (int mt = 0; mt < 2; mt++) {
                uint32_t rowoff = (warp_m * 32 + mt * 16 + (lane & 15)) * PITCHB
                                  + ks * 32 + (lane >> 4) * 16;
                ldmatrix_x4(ahi[mt], sA + rowoff);
                ldmatrix_x4(alo[mt], sA + 10240 + rowoff);
            }
#pragma unroll
            for (int nt = 0; nt < 8; nt++) {
                uint32_t roff = (warp_n * 64 + nt * 8 + gid) * PITCHB + ks * 32 + tg * 4;
                uint32_t bh0 = *(const uint32_t*)(Bh + roff);
                uint32_t bh1 = *(const uint32_t*)(Bh + roff + 16);
                uint32_t bl0 = *(const uint32_t*)(Bl + roff);
                uint32_t bl1 = *(const uint32_t*)(Bl + roff + 16);
                mma_f16(acc[0][nt], ahi[0], bh0, bh1);
                mma_f16(acc[1][nt], ahi[1], bh0, bh1);
                mma_f16(acc[0][nt], alo[0], bh0, bh1);
                mma_f16(acc[1][nt], alo[1], bh0, bh1);
                mma_f16(acc[0][nt], ahi[0], bl0, bl1);
                mma_f16(acc[1][nt], ahi[1], bl0, bl1);
            }
        }
        if (have) {
            char* dA = sm + (buf ^ 1) * BUFS1;
#pragma unroll
            for (int i = 0; i < 4; i++) {
                int row = arow + i * 32;
                *(uint2*)(dA + row * PITCHB + af4 * 8) =
                    make_uint2(pack2hi_h(fa[i].x, fa[i].y), pack2hi_h(fa[i].z, fa[i].w));
                *(uint2*)(dA + 10240 + row * PITCHB + af4 * 8) =
                    make_uint2(pack2lo_h(fa[i].x, fa[i].y), pack2lo_h(fa[i].z, fa[i].w));
            }
        }
        cp_wait0();
        __syncthreads();
    }

    // ---- epilogue: write fp32 result
#pragma unroll
    for (int mt = 0; mt < 2; mt++) {
        int r0 = bm0 + warp_m * 32 + mt * 16 + gid;
        int r1 = r0 + 8;
#pragma unroll
        for (int nt = 0; nt < 8; nt++) {
            int col = bn0 + warp_n * 64 + nt * 8 + tg * 2;
            if (r0 < M)
                *(float2*)(d_xw1 + (size_t)r0 * F1 + col) =
                    make_float2(acc[mt][nt][0], acc[mt][nt][1]);
            if (r1 < M)
                *(float2*)(d_xw1 + (size_t)r1 * F1 + col) =
                    make_float2(acc[mt][nt][2], acc[mt][nt][3]);
        }
    }
}

// ---------------------------------------------------------------------------
// GEMM2 via mma.sync fp16 3-term: hw2 = relu(bn1(h)) @ W2
// BN1 finalize fused at kernel start.
// ---------------------------------------------------------------------------
#define BUFS2 30720
#define SMEM2 (2 * BUFS2)
#define KBLK2 8

__global__ void __launch_bounds__(256, 2)
gemm2_mma_kernel(const float* __restrict__ g1, const float* __restrict__ b1, int M) {
    extern __shared__ __align__(16) char sm[];
    __shared__ float s_sc[F1], s_bi[F1];
    const int tid = threadIdx.x;
    const int wid = tid >> 5;
    const int lane = tid & 31;
    const int gid = lane >> 2;
    const int tg = lane & 3;
    const int bm0 = blockIdx.x * 128;
    const uint32_t sb = smem_u32(sm);

    // fused BN1 finalize
    {
        float inv = 1.f / (float)M;
        float mean = d_sum1[tid] * inv;
        float var = d_sumsq1[tid] * inv - mean * mean;
        float rs = rsqrtf(var + 1e-5f);
        float sc = g1[tid] * rs;
        s_sc[tid] = sc;
        s_bi[tid] = b1[tid] - mean * sc;
    }
    __syncthreads();

    float acc[8][4];
#pragma unroll
    for (int nt = 0; nt < 8; nt++)
#pragma unroll
        for (int q = 0; q < 4; q++) acc[nt][q] = 0.f;

    const int arow = tid >> 3;
    const int af4 = tid & 7;
    const int brow = tid >> 2;
    const int bq = tid & 3;

    auto packA = [&](char* dst, int sk0) {
#pragma unroll
        for (int i = 0; i < 4; i++) {
            int row = arow + i * 32;
            int rg = bm0 + row;
            float4 f = make_float4(0.f, 0.f, 0.f, 0.f);
            if (rg < M) {
                f = __ldcs((const float4*)(d_h + (size_t)rg * F1 + sk0 + af4 * 4));
                int cb = sk0 + af4 * 4;
                f.x = fmaxf(fmaf(f.x, s_sc[cb + 0], s_bi[cb + 0]), 0.f);
                f.y = fmaxf(fmaf(f.y, s_sc[cb + 1], s_bi[cb + 1]), 0.f);
                f.z = fmaxf(fmaf(f.z, s_sc[cb + 2], s_bi[cb + 2]), 0.f);
                f.w = fmaxf(fmaf(f.w, s_sc[cb + 3], s_bi[cb + 3]), 0.f);
            }
            *(uint2*)(dst + row * PITCHB + af4 * 8) =
                make_uint2(pack2hi_h(f.x, f.y), pack2hi_h(f.z, f.w));
            *(uint2*)(dst + 10240 + row * PITCHB + af4 * 8) =
                make_uint2(pack2lo_h(f.x, f.y), pack2lo_h(f.z, f.w));
        }
    };

    packA(sm, 0);
    cp_async16(sb + 20480 + brow * PITCHB + bq * 16, d_B2h + (size_t)brow * F1 + bq * 8);
    cp_async16(sb + 25600 + brow * PITCHB + bq * 16, d_B2l + (size_t)brow * F1 + bq * 8);
    cp_commit();
    cp_wait0();
    __syncthreads();

    for (int c = 0; c < KBLK2; c++) {
        const int buf = c & 1;
        const bool have = (c + 1 < KBLK2);
        if (have) {
            const int sk0 = (c + 1) * 32;
            const uint32_t bb = sb + (buf ^ 1) * BUFS2;
            cp_async16(bb + 20480 + brow * PITCHB + bq * 16,
                       d_B2h + (size_t)brow * F1 + sk0 + bq * 8);
            cp_async16(bb + 25600 + brow * PITCHB + bq * 16,
                       d_B2l + (size_t)brow * F1 + sk0 + bq * 8);
            cp_commit();
        }
        const uint32_t sA = sb + buf * BUFS2;
        const char* Bh = sm + buf * BUFS2 + 20480;
        const char* Bl = sm + buf * BUFS2 + 25600;
#pragma unroll
        for (int ks = 0; ks < 2; ks++) {
            uint32_t ahi[4], alo[4];
            uint32_t rowoff = (wid * 16 + (lane & 15)) * PITCHB + ks * 32 + (lane >> 4) * 16;
            ldmatrix_x4(ahi, sA + rowoff);
            ldmatrix_x4(alo, sA + 10240 + rowoff);
#pragma unroll
            for (int nt = 0; nt < 8; nt++) {
                uint32_t roff = (nt * 8 + gid) * PITCHB + ks * 32 + tg * 4;
                uint32_t bh0 = *(const uint32_t*)(Bh + roff);
                uint32_t bh1 = *(const uint32_t*)(Bh + roff + 16);
                uint32_t bl0 = *(const uint32_t*)(Bl + roff);
                uint32_t bl1 = *(const uint32_t*)(Bl + roff + 16);
                mma_f16(acc[nt], ahi, bh0, bh1);
                mma_f16(acc[nt], alo, bh0, bh1);
                mma_f16(acc[nt], ahi, bl0, bl1);
            }
        }
        if (have) packA(sm + (buf ^ 1) * BUFS2, (c + 1) * 32);
        cp_wait0();
        __syncthreads();
    }

    // ---- epilogue
    int r0 = bm0 + wid * 16 + gid;
    int r1 = r0 + 8;
#pragma unroll
    for (int nt = 0; nt < 8; nt++) {
        int col = nt * 8 + tg * 2;
        if (r0 < M)
            *(float2*)(d_hw2 + (size_t)r0 * F2 + col) = make_float2(acc[nt][0], acc[nt][1]);
        if (r1 < M)
            *(float2*)(d_hw2 + (size_t)r1 * F2 + col) = make_float2(acc[nt][2], acc[nt][3]);
    }
}

// ---------------------------------------------------------------------------
// SpMM1 (persistent): h = relu(A_sparse @ xw1), warp-per-row, edge batching,
// fused BN1 stats. fp32 float4 gathers, unroll 4 (measured optimum).
// ---------------------------------------------------------------------------
__global__ void __launch_bounds__(256) spmm1_kernel(int Nn) {
    __shared__ float redS[8 * 256];
    __shared__ float redQ[8 * 256];
    const int tid = threadIdx.x;
    const int lane = tid & 31;
    const int wloc = tid >> 5;

    float bs[8], bq2[8];
#pragma unroll
    for (int k = 0; k < 8; k++) { bs[k] = 0.f; bq2[k] = 0.f; }

    for (int row = blockIdx.x * 8 + wloc; row < Nn; row += gridDim.x * 8) {
        int s = d_rowptr[row], e = d_rowptr[row + 1];
        float4 a0 = make_float4(0.f, 0.f, 0.f, 0.f);
        float4 a1 = make_float4(0.f, 0.f, 0.f, 0.f);
        for (int base = s; base < e; base += 32) {
            int take = min(32, e - base);
            int cc = 0; float vv = 0.f;
            if (lane < take) { cc = __ldcs(&d_cols[base + lane]); vv = __ldcs(&d_vals[base + lane]); }
            if (take == 32) {
#pragma unroll 4
                for (int j = 0; j < 32; j++) {
                    int c = __shfl_sync(0xffffffffu, cc, j);
                    float v = __shfl_sync(0xffffffffu, vv, j);
                    const float4* p = (const float4*)(d_xw1 + (size_t)c * F1);
                    float4 x0 = __ldg(&p[lane]);
                    float4 x1 = __ldg(&p[lane + 32]);
                    a0.x = fmaf(v, x0.x, a0.x); a0.y = fmaf(v, x0.y, a0.y);
                    a0.z = fmaf(v, x0.z, a0.z); a0.w = fmaf(v, x0.w, a0.w);
                    a1.x = fmaf(v, x1.x, a1.x); a1.y = fmaf(v, x1.y, a1.y);
                    a1.z = fmaf(v, x1.z, a1.z); a1.w = fmaf(v, x1.w, a1.w);
                }
            } else {
                for (int j = 0; j < take; j++) {
                    int c = __shfl_sync(0xffffffffu, cc, j);
                    float v = __shfl_sync(0xffffffffu, vv, j);
                    const float4* p = (const float4*)(d_xw1 + (size_t)c * F1);
                    float4 x0 = __ldg(&p[lane]);
                    float4 x1 = __ldg(&p[lane + 32]);
                    a0.x = fmaf(v, x0.x, a0.x); a0.y = fmaf(v, x0.y, a0.y);
                    a0.z = fmaf(v, x0.z, a0.z); a0.w = fmaf(v, x0.w, a0.w);
                    a1.x = fmaf(v, x1.x, a1.x); a1.y = fmaf(v, x1.y, a1.y);
                    a1.z = fmaf(v, x1.z, a1.z); a1.w = fmaf(v, x1.w, a1.w);
                }
            }
        }
        a0 = make_float4(fmaxf(a0.x, 0.f), fmaxf(a0.y, 0.f), fmaxf(a0.z, 0.f), fmaxf(a0.w, 0.f));
        a1 = make_float4(fmaxf(a1.x, 0.f), fmaxf(a1.y, 0.f), fmaxf(a1.z, 0.f), fmaxf(a1.w, 0.f));
        float4* o = (float4*)(d_h + (size_t)row * F1);
        __stcs(&o[lane], a0);
        __stcs(&o[lane + 32], a1);
        bs[0] += a0.x; bs[1] += a0.y; bs[2] += a0.z; bs[3] += a0.w;
        bs[4] += a1.x; bs[5] += a1.y; bs[6] += a1.z; bs[7] += a1.w;
        bq2[0] = fmaf(a0.x, a0.x, bq2[0]); bq2[1] = fmaf(a0.y, a0.y, bq2[1]);
        bq2[2] = fmaf(a0.z, a0.z, bq2[2]); bq2[3] = fmaf(a0.w, a0.w, bq2[3]);
        bq2[4] = fmaf(a1.x, a1.x, bq2[4]); bq2[5] = fmaf(a1.y, a1.y, bq2[5]);
        bq2[6] = fmaf(a1.z, a1.z, bq2[6]); bq2[7] = fmaf(a1.w, a1.w, bq2[7]);
    }
    // block reduction of BN1 partials (lane owns cols lane*4..+3 and 128+lane*4..+3)
    int base = wloc * 256 + lane * 8;
#pragma unroll
    for (int k = 0; k < 8; k++) { redS[base + k] = bs[k]; redQ[base + k] = bq2[k]; }
    __syncthreads();
    {
        int c = tid;                         // column 0..255
        int l = (c & 127) >> 2;
        int k = ((c >> 7) << 2) | (c & 3);
        float s = 0.f, q = 0.f;
#pragma unroll
        for (int w = 0; w < 8; w++) {
            s += redS[w * 256 + l * 8 + k];
            q += redQ[w * 256 + l * 8 + k];
        }
        atomicAdd(&d_sum1[c], s);
        atomicAdd(&d_sumsq1[c], q);
    }
}

// ---------------------------------------------------------------------------
// SpMM2 (persistent): out = relu(A_sparse @ hw2), fused BN2 stats.
// ---------------------------------------------------------------------------
__global__ void __launch_bounds__(256) spmm2_kernel(float* __restrict__ out, int Nn) {
    __shared__ float redS[8 * 64];
    __shared__ float redQ[8 * 64];
    const int tid = threadIdx.x;
    const int lane = tid & 31;
    const int wloc = tid >> 5;

    float bs0 = 0.f, bs1 = 0.f, bq0 = 0.f, bq1 = 0.f;

    for (int row = blockIdx.x * 8 + wloc; row < Nn; row += gridDim.x * 8) {
        int s = d_rowptr[row], e = d_rowptr[row + 1];
        float2 acc = make_float2(0.f, 0.f);
        for (int base = s; base < e; base += 32) {
            int take = min(32, e - base);
            int cc = 0; float vv = 0.f;
            if (lane < take) { cc = __ldcs(&d_cols[base + lane]); vv = __ldcs(&d_vals[base + lane]); }
            if (take == 32) {
#pragma unroll 4
                for (int j = 0; j < 32; j++) {
                    int c = __shfl_sync(0xffffffffu, cc, j);
                    float v = __shfl_sync(0xffffffffu, vv, j);
                    const float2* p = (const float2*)(d_hw2 + (size_t)c * F2);
                    float2 x0 = __ldg(&p[lane]);
                    acc.x = fmaf(v, x0.x, acc.x);
                    acc.y = fmaf(v, x0.y, acc.y);
                }
            } else {
                for (int j = 0; j < take; j++) {
                    int c = __shfl_sync(0xffffffffu, cc, j);
                    float v = __shfl_sync(0xffffffffu, vv, j);
                    const float2* p = (const float2*)(d_hw2 + (size_t)c * F2);
                    float2 x0 = __ldg(&p[lane]);
                    acc.x = fmaf(v, x0.x, acc.x);
                    acc.y = fmaf(v, x0.y, acc.y);
                }
            }
        }
        acc.x = fmaxf(acc.x, 0.f);
        acc.y = fmaxf(acc.y, 0.f);
        __stcs(&((float2*)(out + (size_t)row * F2))[lane], acc);
        bs0 += acc.x; bs1 += acc.y;
        bq0 = fmaf(acc.x, acc.x, bq0);
        bq1 = fmaf(acc.y, acc.y, bq1);
    }
    int base = wloc * 64 + lane * 2;
    redS[base] = bs0; redS[base + 1] = bs1;
    redQ[base] = bq0; redQ[base + 1] = bq1;
    __syncthreads();
    if (tid < 64) {
        float s = 0.f, q = 0.f;
#pragma unroll
        for (int w = 0; w < 8; w++) {
            s += redS[w * 64 + tid];
            q += redQ[w * 64 + tid];
        }
        atomicAdd(&d_sum2[tid], s);
        atomicAdd(&d_sumsq2[tid], q);
    }
}

// ---------------------------------------------------------------------------
// BN2 finalize + apply in one kernel (in place on d_out)
// ---------------------------------------------------------------------------
__global__ void bnapply2_kernel(float* __restrict__ out,
                                const float* __restrict__ g2,
                                const float* __restrict__ b2,
                                int Nn, int total4) {
    __shared__ float s_sc[F2], s_bi[F2];
    if (threadIdx.x < F2) {
        int c = threadIdx.x;
        float inv = 1.f / (float)Nn;
        float mean = d_sum2[c] * inv;
        float var = d_sumsq2[c] * inv - mean * mean;
        float rs = rsqrtf(var + 1e-5f);
        float sc = g2[c] * rs;
        s_sc[c] = sc;
        s_bi[c] = b2[c] - mean * sc;
    }
    __syncthreads();
    int i = blockIdx.x * blockDim.x + threadIdx.x;
    if (i < total4) {
        int c = (i * 4) & (F2 - 1);
        float4 v = ((float4*)out)[i];
        v.x = fmaf(v.x, s_sc[c + 0], s_bi[c + 0]);
        v.y = fmaf(v.y, s_sc[c + 1], s_bi[c + 1]);
        v.z = fmaf(v.z, s_sc[c + 2], s_bi[c + 2]);
        v.w = fmaf(v.w, s_sc[c + 3], s_bi[c + 3]);
        ((float4*)out)[i] = v;
    }
}

// ---------------------------------------------------------------------------
// Launch sequence: CSR build forked onto a side stream, joined before SpMM1.
// (Converged champion: fp16 3-term HMMA GEMMs, fp32-gather SpMMs with fused
// BN stats, CSR overlap, BN finalizes fused into consumers, cache hints.)
// ---------------------------------------------------------------------------
extern "C" void kernel_launch(void* const* d_in, const int* in_sizes, int n_in,
                              void* d_out, int out_size) {
    const float* x    = (const float*)d_in[0];
    const int*   erow = (const int*)d_in[1];
    const int*   ecol = (const int*)d_in[2];
    const float* evl  = (const float*)d_in[3];
    const float* W1   = (const float*)d_in[4];
    const float* g1   = (const float*)d_in[5];
    const float* b1   = (const float*)d_in[6];
    const float* W2   = (const float*)d_in[7];
    const float* g2   = (const float*)d_in[8];
    const float* b2   = (const float*)d_in[9];
    float* out = (float*)d_out;

    const int Nn = in_sizes[0] / F0;   // 100000
    const int E  = in_sizes[1];        // 3200000
    const int nch = (Nn + 1023) / 1024;

    static cudaStream_t s2 = nullptr;
    static cudaEvent_t evFork = nullptr, evJoin = nullptr;
    static int attr_done = 0;
    if (!attr_done) {
        cudaFuncSetAttribute(gemm1_mma_kernel,
                             cudaFuncAttributeMaxDynamicSharedMemorySize, SMEM1);
        cudaFuncSetAttribute(gemm2_mma_kernel,
                             cudaFuncAttributeMaxDynamicSharedMemorySize, SMEM2);
        cudaStreamCreateWithFlags(&s2, cudaStreamNonBlocking);
        cudaEventCreateWithFlags(&evFork, cudaEventDisableTiming);
        cudaEventCreateWithFlags(&evJoin, cudaEventDisableTiming);
        attr_done = 1;
    }

    // ---- fork: CSR build on s2, GEMM1 path on main stream
    cudaEventRecord(evFork, 0);
    cudaStreamWaitEvent(s2, evFork, 0);

    zero_kernel<<<(Nn + 255) / 256, 256, 0, s2>>>(Nn);
    hist_kernel<<<(E + 255) / 256, 256, 0, s2>>>(erow, E);
    scanA_kernel<<<nch, 1024, 0, s2>>>(Nn);
    scanB_kernel<<<1, 128, 0, s2>>>(nch);
    scanC_kernel<<<(Nn + 255) / 256, 256, 0, s2>>>(Nn, E);
    scatter_kernel<<<(E + 255) / 256, 256, 0, s2>>>(erow, ecol, evl, E);
    cudaEventRecord(evJoin, s2);

    prepW1_kernel<<<(F0 * F1 + 255) / 256, 256>>>(W1);
    prepW2_kernel<<<(F1 * F2 + 255) / 256, 256>>>(W2);
    gemm1_mma_kernel<<<dim3((Nn + 127) / 128, 2), 256, SMEM1>>>(x, Nn);

    // ---- join
    cudaStreamWaitEvent(0, evJoin, 0);

    // Layer 1
    spmm1_kernel<<<1184, 256>>>(Nn);

    // Layer 2 (BN1 finalize fused into GEMM2; BN2 finalize fused into apply)
    gemm2_mma_kernel<<<(Nn + 127) / 128, 256, SMEM2>>>(g1, b1, Nn);
    spmm2_kernel<<<1184, 256>>>(out, Nn);
    bnapply2_kernel<<<(Nn * F2 / 4 + 255) / 256, 256>>>(out, g2, b2, Nn, Nn * F2 / 4);
}